// round 1
// baseline (speedup 1.0000x reference)
#include <cuda_runtime.h>
#include <cuda_bf16.h>

// SmoothLDDTLoss, B=2, N=4096.
// Key reductions:
//  - mask c_lm is identically ~eye(N)  (nuc | ~nuc == True), so is_dna/is_rna and
//    the distance thresholds are dead; denominator is the constant B*N*(N-1).
//  - sum of 4 sigmoids sig(a_i - delta) == 0.25 * P(t)/Q(t), t = exp(delta),
//    with constant polynomial coefficients (c_i = e^{-a_i}):
//      Q(t) = 1 + q1 t + q2 t^2 + q3 t^3 + q4 t^4   (q_k = elem. symm. of c_i)
//      P(t) = 4 + 3 q1 t + 2 q2 t^2 + q3 t^3
//    -> 1 EX2 + 1 RCP + 7 FMA per pair instead of 4 exp + 4 div.
//  - symmetry eps(l,m)=eps(m,l): upper-triangular tiles only, x2 at the end.

constexpr int N    = 4096;
constexpr int B    = 2;
constexpr int TILE = 128;
constexpr int NT   = N / TILE;   // 32

// Polynomial coefficients (c_i = e^{-0.5}, e^{-1}, e^{-2}, e^{-4})
#define Q1 1.1280610230f
#define Q2 0.3753279229f
#define Q3 0.0366994760f
#define Q4 0.0005530844f
#define P1 3.3841830690f   // 3*Q1
#define P2 0.7506558457f   // 2*Q2
#define P3 0.0366994760f   // Q3

__device__ double g_sum;

__global__ void init_k() { g_sum = 0.0; }

__global__ __launch_bounds__(TILE) void lddt_k(const float* __restrict__ x,
                                               const float* __restrict__ xgt) {
    const int bi = blockIdx.x;
    const int bj = blockIdx.y;
    if (bj < bi) return;               // symmetric half only
    const int b = blockIdx.z;

    __shared__ float4 sx[TILE];
    __shared__ float4 sg[TILE];

    const int t = threadIdx.x;
    const float* xb = x   + (size_t)b * N * 3;
    const float* gb = xgt + (size_t)b * N * 3;

    // load m-tile (bj) into shared
    const int mg = bj * TILE + t;
    sx[t] = make_float4(xb[3*mg], xb[3*mg+1], xb[3*mg+2], 0.f);
    sg[t] = make_float4(gb[3*mg], gb[3*mg+1], gb[3*mg+2], 0.f);

    // this thread's l-point in registers
    const int lg = bi * TILE + t;
    const float ax = xb[3*lg], ay = xb[3*lg+1], az = xb[3*lg+2];
    const float gx = gb[3*lg], gy = gb[3*lg+1], gz = gb[3*lg+2];
    __syncthreads();

    const bool diag = (bi == bj);
    float acc = 0.f;

#pragma unroll 8
    for (int m = 0; m < TILE; ++m) {
        const float4 p = sx[m];          // broadcast, conflict-free
        const float4 q = sg[m];
        float dx = ax - p.x, dy = ay - p.y, dz = az - p.z;
        float d1 = fmaf(dx, dx, fmaf(dy, dy, dz * dz));
        float ex = gx - q.x, ey = gy - q.y, ez = gz - q.z;
        float d2 = fmaf(ex, ex, fmaf(ey, ey, ez * ez));
        float delta = fminf(fabsf(d2 - d1), 20.0f);   // clamp: err < 3.4e-8/pair
        float tt = __expf(delta);
        float Qv = fmaf(fmaf(fmaf(fmaf(Q4, tt, Q3), tt, Q2), tt, Q1), tt, 1.0f);
        float Pv = fmaf(fmaf(fmaf(P3, tt, P2), tt, P1), tt, 4.0f);
        float eps = 0.25f * Pv * __fdividef(1.0f, Qv);
        // diagonal tile: keep strictly m > t (excludes l==m and the lower half)
        bool take = (!diag) | (m > t);
        acc += take ? eps : 0.0f;
    }

    // block reduction: warp shuffle, then cross-warp, one atomic per block
#pragma unroll
    for (int o = 16; o > 0; o >>= 1)
        acc += __shfl_xor_sync(0xffffffff, acc, o);

    __shared__ float warp_sums[TILE / 32];
    if ((t & 31) == 0) warp_sums[t >> 5] = acc;
    __syncthreads();
    if (t == 0) {
        float s = 0.f;
#pragma unroll
        for (int w = 0; w < TILE / 32; ++w) s += warp_sums[w];
        atomicAdd(&g_sum, (double)s);
    }
}

__global__ void fin_k(float* __restrict__ out) {
    const double cnt = (double)B * N * (N - 1);   // 33,546,240
    out[0] = (float)(1.0 - 2.0 * g_sum / cnt);
}

extern "C" void kernel_launch(void* const* d_in, const int* in_sizes, int n_in,
                              void* d_out, int out_size) {
    const float* x   = (const float*)d_in[0];
    const float* xgt = (const float*)d_in[1];
    // d_in[2] (is_dna), d_in[3] (is_rna) are provably dead: c_lm == ~eye(N).
    init_k<<<1, 1>>>();
    dim3 grid(NT, NT, B);
    lddt_k<<<grid, TILE>>>(x, xgt);
    fin_k<<<1, 1>>>((float*)d_out);
}

// round 2
// speedup vs baseline: 1.3842x; 1.3842x over previous
#include <cuda_runtime.h>
#include <cuda_bf16.h>

// SmoothLDDTLoss, B=2, N=4096 — single fused kernel.
//
// Math reductions:
//  - c_lm mask is identically ~eye(N) (nuc | ~nuc == True) -> is_dna/is_rna dead,
//    denominator = B*N*(N-1) constant.
//  - sum of 4 sigmoids sig(a_i - d) = P(t)/Q(t), t = e^d:
//      Q(t) = 1 + e1 t + e2 t^2 + e3 t^3 + e4 t^4   (e_k elem. symmetric of e^{-a_i})
//      0.25*P(t) = 1 + 0.75 e1 t + 0.5 e2 t^2 + 0.25 e3 t^3
//  - d*log2e computed via expanded form: sL_l + sL_m - g_l.(2L g_m) + x_l.(2L x_m)
//    (per-point norms/scales precomputed; ex2.approx directly, no range fixup)
//  - symmetry: upper-triangular tiles only, x2 at the end.

constexpr int N    = 4096;
constexpr int B    = 2;
constexpr int TILE = 128;
constexpr int NT   = N / TILE;           // 32
constexpr int TRI  = NT * (NT + 1) / 2;  // 528
constexpr int GRID = TRI * B;            // 1056

// Q coefficients (elementary symmetric of e^{-0.5}, e^{-1}, e^{-2}, e^{-4})
#define QC1 1.1280610230f
#define QC2 0.3753279229f
#define QC3 0.0366994760f
#define QC4 0.0005530844f
// 0.25*P coefficients
#define PC1 0.8460457673f   // 0.75*QC1
#define PC2 0.1876639614f   // 0.50*QC2
#define PC3 0.0091748690f   // 0.25*QC3

#define LOG2E  1.4426950408889634f
#define DCLAMP 28.8539008178f           // 20 * log2e

__device__ float        g_part[GRID];
__device__ unsigned int g_cnt = 0;

__device__ __forceinline__ float pair_eps(float sLl,
                                          float lg0, float lg1, float lg2,
                                          float lx0, float lx1, float lx2,
                                          const float4& A, const float4& Bv) {
    // r = (dGT - dx) * log2e
    float r = sLl + A.w;
    r = fmaf(lg0, -A.x, r);
    r = fmaf(lg1, -A.y, r);
    r = fmaf(lg2, -A.z, r);
    r = fmaf(lx0,  Bv.x, r);
    r = fmaf(lx1,  Bv.y, r);
    r = fmaf(lx2,  Bv.z, r);
    float d = fminf(fabsf(r), DCLAMP);
    float t;  asm("ex2.approx.f32 %0, %1;" : "=f"(t) : "f"(d));
    float Qv = fmaf(fmaf(fmaf(fmaf(QC4, t, QC3), t, QC2), t, QC1), t, 1.0f);
    float Pv = fmaf(fmaf(fmaf(PC3, t, PC2), t, PC1), t, 1.0f);
    float rQ; asm("rcp.approx.f32 %0, %1;" : "=f"(rQ) : "f"(Qv));
    return Pv * rQ;   // caller folds into acc (ptxas fuses mul+add -> ffma)
}

__global__ __launch_bounds__(TILE) void lddt_k(const float* __restrict__ x,
                                               const float* __restrict__ xgt,
                                               float* __restrict__ out) {
    const int p = blockIdx.x;
    const int b = p / TRI;
    int rem = p - b * TRI;
    int bi = 0;
    while (rem >= NT - bi) { rem -= NT - bi; ++bi; }
    const int bj = bi + rem;

    const float* xb = x   + (size_t)b * N * 3;
    const float* gb = xgt + (size_t)b * N * 3;
    const int t = threadIdx.x;

    __shared__ float4 sA[TILE];   // (2L*gm0, 2L*gm1, 2L*gm2, L*(|gm|^2-|xm|^2))
    __shared__ float4 sB[TILE];   // (2L*xm0, 2L*xm1, 2L*xm2, 0)

    // m-side (tile bj), scaled into shared
    {
        const int mg = bj * TILE + t;
        float mx0 = xb[3*mg], mx1 = xb[3*mg+1], mx2 = xb[3*mg+2];
        float mg0 = gb[3*mg], mg1 = gb[3*mg+1], mg2 = gb[3*mg+2];
        float sm = fmaf(mg0, mg0, fmaf(mg1, mg1, mg2*mg2))
                 - fmaf(mx0, mx0, fmaf(mx1, mx1, mx2*mx2));
        sA[t] = make_float4(2.0f*LOG2E*mg0, 2.0f*LOG2E*mg1, 2.0f*LOG2E*mg2, LOG2E*sm);
        sB[t] = make_float4(2.0f*LOG2E*mx0, 2.0f*LOG2E*mx1, 2.0f*LOG2E*mx2, 0.0f);
    }

    // l-side (tile bi), raw in registers
    const int lg = bi * TILE + t;
    const float lx0 = xb[3*lg], lx1 = xb[3*lg+1], lx2 = xb[3*lg+2];
    const float lg0 = gb[3*lg], lg1 = gb[3*lg+1], lg2 = gb[3*lg+2];
    const float sLl = LOG2E * (fmaf(lg0, lg0, fmaf(lg1, lg1, lg2*lg2))
                             - fmaf(lx0, lx0, fmaf(lx1, lx1, lx2*lx2)));
    __syncthreads();

    float acc0 = 0.f, acc1 = 0.f;
    if (bi != bj) {
#pragma unroll 8
        for (int m = 0; m < TILE; m += 2) {
            acc0 += pair_eps(sLl, lg0, lg1, lg2, lx0, lx1, lx2, sA[m],   sB[m]);
            acc1 += pair_eps(sLl, lg0, lg1, lg2, lx0, lx1, lx2, sA[m+1], sB[m+1]);
        }
    } else {
#pragma unroll 8
        for (int m = 0; m < TILE; ++m) {
            float e = pair_eps(sLl, lg0, lg1, lg2, lx0, lx1, lx2, sA[m], sB[m]);
            if (m > t) acc0 += e;   // strict upper: excludes diagonal l==m
        }
    }
    float acc = acc0 + acc1;

    // block reduce
#pragma unroll
    for (int o = 16; o > 0; o >>= 1)
        acc += __shfl_xor_sync(0xffffffffu, acc, o);

    __shared__ float ws[TILE / 32];
    __shared__ bool  is_last;
    if ((t & 31) == 0) ws[t >> 5] = acc;
    __syncthreads();
    if (t == 0) {
        g_part[p] = ws[0] + ws[1] + ws[2] + ws[3];
        __threadfence();
        unsigned old = atomicAdd(&g_cnt, 1u);
        is_last = (old == GRID - 1);
    }
    __syncthreads();

    // last block finalizes (deterministic sum order) and resets the counter
    if (is_last) {
        float s = 0.f;
        for (int i = t; i < GRID; i += TILE)
            s += *((volatile float*)&g_part[i]);
#pragma unroll
        for (int o = 16; o > 0; o >>= 1)
            s += __shfl_xor_sync(0xffffffffu, s, o);
        if ((t & 31) == 0) ws[t >> 5] = s;
        __syncthreads();
        if (t == 0) {
            double S = (double)ws[0] + ws[1] + ws[2] + ws[3];
            const double cnt = (double)B * N * (N - 1);   // 33,546,240
            out[0] = (float)(1.0 - 2.0 * S / cnt);
            g_cnt = 0;   // reset for next graph replay
        }
    }
}

extern "C" void kernel_launch(void* const* d_in, const int* in_sizes, int n_in,
                              void* d_out, int out_size) {
    const float* x   = (const float*)d_in[0];
    const float* xgt = (const float*)d_in[1];
    // d_in[2] (is_dna), d_in[3] (is_rna) are provably dead: c_lm == ~eye(N).
    lddt_k<<<GRID, TILE>>>(x, xgt, (float*)d_out);
}